// round 2
// baseline (speedup 1.0000x reference)
#include <cuda_runtime.h>
#include <cuda_bf16.h>
#include <float.h>

// Problem constants
#define V_   32000
#define C_   1024
#define H_   16
#define L_   8
#define F_   4096
#define B_   2
#define T_   2048
#define D_   64
#define BT_  (B_*T_)

// ---------------------------------------------------------------------------
// Scratch (static device arrays; no allocation allowed)
// ---------------------------------------------------------------------------
__device__ float g_x  [BT_ * C_];
__device__ float g_h  [BT_ * C_];
__device__ float g_q  [BT_ * C_];
__device__ float g_k  [BT_ * C_];
__device__ float g_v  [BT_ * C_];
__device__ float g_ao [BT_ * C_];
__device__ float g_hid[BT_ * F_];
__device__ float g_xf [B_ * C_];

// ---------------------------------------------------------------------------
// Embedding: x[b,t,:] = emb[idx[b,t],:] + pos[t,:]
// grid = BT_, block = 256 (each thread 1 float4)
// ---------------------------------------------------------------------------
__global__ void embed_kernel(const int* __restrict__ idx,
                             const float* __restrict__ emb,
                             const float* __restrict__ pos,
                             float* __restrict__ x) {
    int row = blockIdx.x;
    int t   = row % T_;
    int tok = idx[row];
    int c   = threadIdx.x * 4;
    float4 e = *(const float4*)(emb + (size_t)tok * C_ + c);
    float4 p = *(const float4*)(pos + (size_t)t   * C_ + c);
    float4 o;
    o.x = e.x + p.x; o.y = e.y + p.y; o.z = e.z + p.z; o.w = e.w + p.w;
    *(float4*)(x + (size_t)row * C_ + c) = o;
}

// ---------------------------------------------------------------------------
// LayerNorm over C=1024. block = 256 threads, 1 row per block.
// LAST=true: input row = blockIdx.x*T_ + (T_-1), output row = blockIdx.x.
// ---------------------------------------------------------------------------
template<bool LAST>
__global__ void layernorm_kernel(const float* __restrict__ x,
                                 const float* __restrict__ g,
                                 const float* __restrict__ b,
                                 float* __restrict__ y) {
    int row_in  = LAST ? (blockIdx.x * T_ + (T_ - 1)) : blockIdx.x;
    int row_out = blockIdx.x;
    int tid = threadIdx.x;
    int c = tid * 4;

    float4 xv = *(const float4*)(x + (size_t)row_in * C_ + c);
    float s  = xv.x + xv.y + xv.z + xv.w;
    float sq = xv.x*xv.x + xv.y*xv.y + xv.z*xv.z + xv.w*xv.w;

    __shared__ float ssum[256];
    __shared__ float ssq[256];
    ssum[tid] = s; ssq[tid] = sq;
    __syncthreads();
    #pragma unroll
    for (int st = 128; st > 0; st >>= 1) {
        if (tid < st) { ssum[tid] += ssum[tid+st]; ssq[tid] += ssq[tid+st]; }
        __syncthreads();
    }
    __shared__ float s_mean, s_rstd;
    if (tid == 0) {
        float mean = ssum[0] * (1.0f / C_);
        float var  = ssq[0] * (1.0f / C_) - mean * mean;
        s_mean = mean;
        s_rstd = rsqrtf(var + 1e-5f);
    }
    __syncthreads();
    float mean = s_mean, rstd = s_rstd;

    float4 gv = *(const float4*)(g + c);
    float4 bv = *(const float4*)(b + c);
    float4 o;
    o.x = (xv.x - mean) * rstd * gv.x + bv.x;
    o.y = (xv.y - mean) * rstd * gv.y + bv.y;
    o.z = (xv.z - mean) * rstd * gv.z + bv.z;
    o.w = (xv.w - mean) * rstd * gv.w + bv.w;
    *(float4*)(y + (size_t)row_out * C_ + c) = o;
}

// ---------------------------------------------------------------------------
// SGEMM: C = A[MxK] @ B[KxN] + bias (+ optional ReLU, + optional residual)
// 128x128 block tile, K-slice 16, 256 threads, 8x8 per-thread microtile.
// All dims divisible by tile sizes in this problem.
// ---------------------------------------------------------------------------
template<bool RELU, bool RES>
__global__ __launch_bounds__(256, 2)
void sgemm_kernel(const float* __restrict__ A, const float* __restrict__ B,
                  const float* __restrict__ bias, const float* __restrict__ res,
                  float* __restrict__ C, int M, int N, int K) {
    __shared__ float As[16][128];   // [k][m]
    __shared__ float Bs[16][128];   // [k][n]

    const int tid = threadIdx.x;
    const int tx = tid & 15;        // 0..15 -> 8 cols each
    const int ty = tid >> 4;        // 0..15 -> 8 rows each
    const int m0 = blockIdx.y * 128;
    const int n0 = blockIdx.x * 128;

    float acc[8][8];
    #pragma unroll
    for (int i = 0; i < 8; i++)
        #pragma unroll
        for (int j = 0; j < 8; j++) acc[i][j] = 0.0f;

    const int nkt = K >> 4;
    for (int kt = 0; kt < nkt; kt++) {
        // load A tile (128 rows x 16 cols) -> As transposed
        #pragma unroll
        for (int r = 0; r < 2; r++) {
            int idx = tid + r * 256;            // 0..511
            int row = idx >> 2;                 // 0..127
            int c4  = idx & 3;                  // 0..3
            float4 av = *(const float4*)(A + (size_t)(m0 + row) * K + kt * 16 + c4 * 4);
            As[c4*4 + 0][row] = av.x;
            As[c4*4 + 1][row] = av.y;
            As[c4*4 + 2][row] = av.z;
            As[c4*4 + 3][row] = av.w;
        }
        // load B tile (16 rows x 128 cols)
        #pragma unroll
        for (int r = 0; r < 2; r++) {
            int idx = tid + r * 256;            // 0..511
            int row = idx >> 5;                 // 0..15
            int c4  = idx & 31;                 // 0..31
            float4 bv = *(const float4*)(B + (size_t)(kt * 16 + row) * N + n0 + c4 * 4);
            *(float4*)&Bs[row][c4 * 4] = bv;
        }
        __syncthreads();

        #pragma unroll
        for (int k = 0; k < 16; k++) {
            float4 a0 = *(float4*)&As[k][ty * 8];
            float4 a1 = *(float4*)&As[k][ty * 8 + 4];
            float4 b0 = *(float4*)&Bs[k][tx * 8];
            float4 b1 = *(float4*)&Bs[k][tx * 8 + 4];
            float ar[8] = {a0.x,a0.y,a0.z,a0.w,a1.x,a1.y,a1.z,a1.w};
            float br[8] = {b0.x,b0.y,b0.z,b0.w,b1.x,b1.y,b1.z,b1.w};
            #pragma unroll
            for (int i = 0; i < 8; i++)
                #pragma unroll
                for (int j = 0; j < 8; j++)
                    acc[i][j] = fmaf(ar[i], br[j], acc[i][j]);
        }
        __syncthreads();
    }

    // epilogue
    const int nbase = n0 + tx * 8;
    float4 bias0 = *(const float4*)(bias + nbase);
    float4 bias1 = *(const float4*)(bias + nbase + 4);
    #pragma unroll
    for (int i = 0; i < 8; i++) {
        int m = m0 + ty * 8 + i;
        float4 v0, v1;
        v0.x = acc[i][0] + bias0.x; v0.y = acc[i][1] + bias0.y;
        v0.z = acc[i][2] + bias0.z; v0.w = acc[i][3] + bias0.w;
        v1.x = acc[i][4] + bias1.x; v1.y = acc[i][5] + bias1.y;
        v1.z = acc[i][6] + bias1.z; v1.w = acc[i][7] + bias1.w;
        if (RELU) {
            v0.x = fmaxf(v0.x, 0.f); v0.y = fmaxf(v0.y, 0.f);
            v0.z = fmaxf(v0.z, 0.f); v0.w = fmaxf(v0.w, 0.f);
            v1.x = fmaxf(v1.x, 0.f); v1.y = fmaxf(v1.y, 0.f);
            v1.z = fmaxf(v1.z, 0.f); v1.w = fmaxf(v1.w, 0.f);
        }
        if (RES) {
            float4 r0 = *(const float4*)(res + (size_t)m * N + nbase);
            float4 r1 = *(const float4*)(res + (size_t)m * N + nbase + 4);
            v0.x += r0.x; v0.y += r0.y; v0.z += r0.z; v0.w += r0.w;
            v1.x += r1.x; v1.y += r1.y; v1.z += r1.z; v1.w += r1.w;
        }
        *(float4*)(C + (size_t)m * N + nbase)     = v0;
        *(float4*)(C + (size_t)m * N + nbase + 4) = v1;
    }
}

// ---------------------------------------------------------------------------
// Causal flash attention, fp32. One warp per query; block = 4 warps handling
// 4 consecutive queries of the same (b,h); 32-key SMEM tiles shared in block.
// q,k,v,o layout: (B*T, C) with C = H*D; head h slice at offset h*D.
// ---------------------------------------------------------------------------
__global__ __launch_bounds__(128)
void attention_kernel(const float* __restrict__ q, const float* __restrict__ k,
                      const float* __restrict__ v, float* __restrict__ o) {
    __shared__ float Ks[32][68];   // padded: 17 float4/row (odd -> conflict-free)
    __shared__ float Vs[32][68];

    const int b  = blockIdx.z;
    const int h  = blockIdx.y;
    const int t0 = blockIdx.x * 4;
    const int w    = threadIdx.x >> 5;
    const int lane = threadIdx.x & 31;
    const int t = t0 + w;

    // load q row, fold in softmax scale 1/sqrt(64)
    const float* qp = q + ((size_t)(b * T_ + t) * C_ + h * D_);
    float4 qr[16];
    #pragma unroll
    for (int i = 0; i < 16; i++) {
        float4 qv = *(const float4*)(qp + i * 4);
        qr[i].x = qv.x * 0.125f; qr[i].y = qv.y * 0.125f;
        qr[i].z = qv.z * 0.125f; qr[i].w = qv.w * 0.125f;
    }

    float4 orr[16];
    #pragma unroll
    for (int i = 0; i < 16; i++) orr[i] = make_float4(0.f, 0.f, 0.f, 0.f);
    float m = -FLT_MAX, l = 0.0f;

    const int nkb = (t0 + 3) / 32 + 1;
    const size_t kv_head_off = (size_t)h * D_;

    for (int kb = 0; kb < nkb; kb++) {
        __syncthreads();   // protect previous tile use
        // cooperative load of 32 keys x 64 dims (K and V)
        #pragma unroll
        for (int r = 0; r < 4; r++) {
            int idx  = threadIdx.x + r * 128;   // 0..511
            int key  = idx >> 4;                // 0..31
            int c4   = idx & 15;                // 0..15
            size_t goff = (size_t)(b * T_ + kb * 32 + key) * C_ + kv_head_off + c4 * 4;
            *(float4*)&Ks[key][c4 * 4] = *(const float4*)(k + goff);
            *(float4*)&Vs[key][c4 * 4] = *(const float4*)(v + goff);
        }
        __syncthreads();

        // score for this lane's key
        float s = 0.0f;
        #pragma unroll
        for (int i = 0; i < 16; i++) {
            float4 kk = *(float4*)&Ks[lane][i * 4];
            s = fmaf(qr[i].x, kk.x, s);
            s = fmaf(qr[i].y, kk.y, s);
            s = fmaf(qr[i].z, kk.z, s);
            s = fmaf(qr[i].w, kk.w, s);
        }
        int kidx = kb * 32 + lane;
        bool masked = (kidx > t);
        if (masked) s = -FLT_MAX;

        // warp max
        float mloc = s;
        #pragma unroll
        for (int off = 16; off; off >>= 1)
            mloc = fmaxf(mloc, __shfl_xor_sync(0xffffffffu, mloc, off));
        float mnew = fmaxf(m, mloc);
        float alpha = __expf(m - mnew);          // m=-FLT_MAX first iter -> 0
        float p = masked ? 0.0f : __expf(s - mnew);

        float psum = p;
        #pragma unroll
        for (int off = 16; off; off >>= 1)
            psum += __shfl_xor_sync(0xffffffffu, psum, off);

        l = l * alpha + psum;
        m = mnew;

        #pragma unroll
        for (int i = 0; i < 16; i++) {
            float4 vv = *(float4*)&Vs[lane][i * 4];
            orr[i].x = fmaf(p, vv.x, orr[i].x * alpha);
            orr[i].y = fmaf(p, vv.y, orr[i].y * alpha);
            orr[i].z = fmaf(p, vv.z, orr[i].z * alpha);
            orr[i].w = fmaf(p, vv.w, orr[i].w * alpha);
        }
    }

    // reduce o across lanes (butterfly all-reduce), lane 0 writes
    #pragma unroll
    for (int i = 0; i < 16; i++) {
        #pragma unroll
        for (int off = 16; off; off >>= 1) {
            orr[i].x += __shfl_xor_sync(0xffffffffu, orr[i].x, off);
            orr[i].y += __shfl_xor_sync(0xffffffffu, orr[i].y, off);
            orr[i].z += __shfl_xor_sync(0xffffffffu, orr[i].z, off);
            orr[i].w += __shfl_xor_sync(0xffffffffu, orr[i].w, off);
        }
    }
    if (lane == 0) {
        float inv = 1.0f / l;
        float* op = o + ((size_t)(b * T_ + t) * C_ + h * D_);
        #pragma unroll
        for (int i = 0; i < 16; i++) {
            float4 ov;
            ov.x = orr[i].x * inv; ov.y = orr[i].y * inv;
            ov.z = orr[i].z * inv; ov.w = orr[i].w * inv;
            *(float4*)(op + i * 4) = ov;
        }
    }
}

// ---------------------------------------------------------------------------
// Logits: out[b,v] = dot(xf[b,:], W[:,v]) + out_b[v]
// grid (V/128, B), block 128
// ---------------------------------------------------------------------------
__global__ void logits_kernel(const float* __restrict__ xf,
                              const float* __restrict__ W,
                              const float* __restrict__ bias,
                              float* __restrict__ out) {
    __shared__ float xs[C_];
    const int b = blockIdx.y;
    const int tid = threadIdx.x;
    #pragma unroll
    for (int r = 0; r < C_ / 128; r++)
        xs[tid + r * 128] = xf[b * C_ + tid + r * 128];
    __syncthreads();

    int vcol = blockIdx.x * 128 + tid;
    float acc = bias[vcol];
    const float* wp = W + vcol;
    #pragma unroll 8
    for (int k = 0; k < C_; k++)
        acc = fmaf(xs[k], wp[(size_t)k * V_], acc);
    out[(size_t)b * V_ + vcol] = acc;
}

// ---------------------------------------------------------------------------
// Launch
// ---------------------------------------------------------------------------
extern "C" void kernel_launch(void* const* d_in, const int* in_sizes, int n_in,
                              void* d_out, int out_size) {
    const int*   idx   = (const int*)  d_in[0];
    const float* emb   = (const float*)d_in[1];
    const float* pos   = (const float*)d_in[2];
    const float* ln1_g = (const float*)d_in[3];
    const float* ln1_b = (const float*)d_in[4];
    const float* wq    = (const float*)d_in[5];
    const float* bq    = (const float*)d_in[6];
    const float* wk    = (const float*)d_in[7];
    const float* bk    = (const float*)d_in[8];
    const float* wv    = (const float*)d_in[9];
    const float* bv    = (const float*)d_in[10];
    const float* wo    = (const float*)d_in[11];
    const float* bo    = (const float*)d_in[12];
    const float* ln2_g = (const float*)d_in[13];
    const float* ln2_b = (const float*)d_in[14];
    const float* w1    = (const float*)d_in[15];
    const float* b1    = (const float*)d_in[16];
    const float* w2    = (const float*)d_in[17];
    const float* b2    = (const float*)d_in[18];
    const float* lnf_g = (const float*)d_in[19];
    const float* lnf_b = (const float*)d_in[20];
    const float* out_w = (const float*)d_in[21];
    const float* out_b = (const float*)d_in[22];
    float* out = (float*)d_out;

    float *x, *h, *q, *k, *v, *ao, *hid, *xf;
    cudaGetSymbolAddress((void**)&x,   g_x);
    cudaGetSymbolAddress((void**)&h,   g_h);
    cudaGetSymbolAddress((void**)&q,   g_q);
    cudaGetSymbolAddress((void**)&k,   g_k);
    cudaGetSymbolAddress((void**)&v,   g_v);
    cudaGetSymbolAddress((void**)&ao,  g_ao);
    cudaGetSymbolAddress((void**)&hid, g_hid);
    cudaGetSymbolAddress((void**)&xf,  g_xf);

    embed_kernel<<<BT_, 256>>>(idx, emb, pos, x);

    dim3 gemm_cc(C_ / 128, BT_ / 128);   // (8, 32)
    dim3 gemm_cf(F_ / 128, BT_ / 128);   // (32, 32)
    dim3 attn_grid(T_ / 4, H_, B_);      // (512, 16, 2)

    for (int l = 0; l < L_; l++) {
        layernorm_kernel<false><<<BT_, 256>>>(x, ln1_g + l * C_, ln1_b + l * C_, h);

        sgemm_kernel<false, false><<<gemm_cc, 256>>>(h, wq + (size_t)l * C_ * C_, bq + l * C_, nullptr, q, BT_, C_, C_);
        sgemm_kernel<false, false><<<gemm_cc, 256>>>(h, wk + (size_t)l * C_ * C_, bk + l * C_, nullptr, k, BT_, C_, C_);
        sgemm_kernel<false, false><<<gemm_cc, 256>>>(h, wv + (size_t)l * C_ * C_, bv + l * C_, nullptr, v, BT_, C_, C_);

        attention_kernel<<<attn_grid, 128>>>(q, k, v, ao);

        // x = x + (ao @ wo + bo)
        sgemm_kernel<false, true><<<gemm_cc, 256>>>(ao, wo + (size_t)l * C_ * C_, bo + l * C_, x, x, BT_, C_, C_);

        layernorm_kernel<false><<<BT_, 256>>>(x, ln2_g + l * C_, ln2_b + l * C_, h);

        // hid = relu(h @ w1 + b1)
        sgemm_kernel<true, false><<<gemm_cf, 256>>>(h, w1 + (size_t)l * C_ * F_, b1 + l * F_, nullptr, hid, BT_, F_, C_);
        // x = x + (hid @ w2 + b2)
        sgemm_kernel<false, true><<<gemm_cc, 256>>>(hid, w2 + (size_t)l * F_ * C_, b2 + l * C_, x, x, BT_, C_, F_);
    }

    layernorm_kernel<true><<<B_, 256>>>(x, lnf_g, lnf_b, xf);
    logits_kernel<<<dim3(V_ / 128, B_), 128>>>(xf, out_w, out_b, out);
}